// round 3
// baseline (speedup 1.0000x reference)
#include <cuda_runtime.h>
#include <math.h>

// ---------------------------------------------------------------------------
// DBS_lstm: 3-layer LSTM (T=512, H=1024, batch=1) + output projection.
//   per layer: xg = h_prev @ W_ih^T + (b_ih+b_hh)      (sgemm128)
//              recurrence over t                        (lstm_layer_kernel)
//   final:     out = hs2 @ W_out^T                      (sgemm128)
// ---------------------------------------------------------------------------

#define T_FRAMES 512
#define HID      1024
#define GATES    (4 * HID)
#define IN_DIM   85
#define OUT_N    (6890 * 3)
#define NCTA     128
#define NTHR     256

// --------------------------- scratch (device globals) ----------------------
__device__ float    g_xg[T_FRAMES * GATES];
__device__ float    g_hsA[T_FRAMES * HID];
__device__ float    g_hsB[T_FRAMES * HID];
__device__ unsigned g_cnt[T_FRAMES];          // per-timestep arrival counters

// ======================= SGEMM: C = A @ B^T (+bias) =========================
// A:[M,K] rm, B:[N,K] rm, C:[M,N] rm.  128x128 tile, 8x8 micro, BK=8,
// double-buffered smem with register prefetch.
#define BM  128
#define BN  128
#define BKs 8
#define LDP 132   // padded tile pitch (conflict-free transposed STS)

__global__ __launch_bounds__(256)
void sgemm128(const float* __restrict__ A, const float* __restrict__ B,
              const float* __restrict__ b0, const float* __restrict__ b1,
              float* __restrict__ C, int M, int N, int K,
              unsigned* cnt_reset)
{
    __shared__ float As[2][BKs][LDP];
    __shared__ float Bs[2][BKs][LDP];

    const int tid = threadIdx.x;

    // Reset the LSTM step counters for the recurrence kernel that follows.
    if (cnt_reset && blockIdx.x == 0 && blockIdx.y == 0) {
        cnt_reset[tid]       = 0u;
        cnt_reset[tid + 256] = 0u;
    }

    const int m0 = blockIdx.y * BM;
    const int n0 = blockIdx.x * BN;
    const int lr = tid >> 1;            // 0..127
    const int lk = (tid & 1) << 2;      // 0 or 4
    const int tx = tid & 15;
    const int ty = tid >> 4;
    const bool vec4 = ((K & 3) == 0);

    float acc[8][8];
#pragma unroll
    for (int i = 0; i < 8; ++i)
#pragma unroll
        for (int j = 0; j < 8; ++j) acc[i][j] = 0.f;

    float pa[4], pb[4];

#define LOAD_A(k0)                                                          \
    {                                                                       \
        const int m = m0 + lr;                                              \
        const int k = (k0) + lk;                                            \
        if (m < M && vec4 && (k + 3) < K) {                                 \
            const float4 v = *(const float4*)(A + (size_t)m * K + k);       \
            pa[0] = v.x; pa[1] = v.y; pa[2] = v.z; pa[3] = v.w;             \
        } else {                                                            \
            _Pragma("unroll")                                               \
            for (int j = 0; j < 4; ++j)                                     \
                pa[j] = (m < M && (k + j) < K) ? A[(size_t)m * K + k + j]   \
                                               : 0.f;                       \
        }                                                                   \
    }
#define LOAD_B(k0)                                                          \
    {                                                                       \
        const int n = n0 + lr;                                              \
        const int k = (k0) + lk;                                            \
        if (n < N && vec4 && (k + 3) < K) {                                 \
            const float4 v = *(const float4*)(B + (size_t)n * K + k);       \
            pb[0] = v.x; pb[1] = v.y; pb[2] = v.z; pb[3] = v.w;             \
        } else {                                                            \
            _Pragma("unroll")                                               \
            for (int j = 0; j < 4; ++j)                                     \
                pb[j] = (n < N && (k + j) < K) ? B[(size_t)n * K + k + j]   \
                                               : 0.f;                      \
        }                                                                   \
    }
#define STS_TILE(buf)                                                       \
    {                                                                       \
        _Pragma("unroll")                                                   \
        for (int j = 0; j < 4; ++j) {                                       \
            As[buf][lk + j][lr] = pa[j];                                    \
            Bs[buf][lk + j][lr] = pb[j];                                    \
        }                                                                   \
    }
#define COMPUTE(buf)                                                        \
    {                                                                       \
        _Pragma("unroll")                                                   \
        for (int kk = 0; kk < BKs; ++kk) {                                  \
            const float4 a0 = *(const float4*)&As[buf][kk][ty * 4];         \
            const float4 a1 = *(const float4*)&As[buf][kk][64 + ty * 4];    \
            const float4 q0 = *(const float4*)&Bs[buf][kk][tx * 4];         \
            const float4 q1 = *(const float4*)&Bs[buf][kk][64 + tx * 4];    \
            const float av[8] = {a0.x, a0.y, a0.z, a0.w,                    \
                                 a1.x, a1.y, a1.z, a1.w};                   \
            const float bv[8] = {q0.x, q0.y, q0.z, q0.w,                    \
                                 q1.x, q1.y, q1.z, q1.w};                   \
            _Pragma("unroll")                                               \
            for (int i = 0; i < 8; ++i)                                     \
                _Pragma("unroll")                                           \
                for (int j = 0; j < 8; ++j)                                 \
                    acc[i][j] = fmaf(av[i], bv[j], acc[i][j]);              \
        }                                                                   \
    }

    int buf = 0;
    LOAD_A(0); LOAD_B(0);
    STS_TILE(0);
    __syncthreads();

    for (int k0 = BKs; k0 < K; k0 += BKs) {
        LOAD_A(k0); LOAD_B(k0);        // prefetch next tile to registers
        COMPUTE(buf);                  // compute on current smem buffer
        const int nb = buf ^ 1;
        STS_TILE(nb);
        __syncthreads();
        buf = nb;
    }
    COMPUTE(buf);

    // ---- epilogue ----
#pragma unroll
    for (int i = 0; i < 8; ++i) {
        const int m = m0 + ((i < 4) ? (ty * 4 + i) : (64 + ty * 4 + i - 4));
        if (m >= M) continue;
#pragma unroll
        for (int j = 0; j < 8; ++j) {
            const int n = n0 + ((j < 4) ? (tx * 4 + j) : (64 + tx * 4 + j - 4));
            if (n >= N) continue;
            float v = acc[i][j];
            if (b0) v += __ldg(&b0[n]);
            if (b1) v += __ldg(&b1[n]);
            C[(size_t)m * N + n] = v;
        }
    }
#undef LOAD_A
#undef LOAD_B
#undef STS_TILE
#undef COMPUTE
}

// ======================= persistent LSTM recurrence =========================
// 128 CTAs (1/SM), 256 threads. CTA owns 8 hidden units => 32 rows of W_hh
// (4 gates x 8 units), each row split over 8 lanes (128 weights/lane in regs).
// h_t is published directly into hs_out (L2) with per-step arrival counters;
// consumers poll the counter (one ldg per warp) and then fetch the row.

__device__ __forceinline__ float sigmf(float x) { return 1.f / (1.f + expf(-x)); }

__global__ __launch_bounds__(NTHR, 1)
void lstm_layer_kernel(const float* __restrict__ Whh,   // [4096,1024]
                       const float* __restrict__ xg,    // [512,4096] (w/ biases)
                       float* __restrict__ hs_out,      // [512,1024]
                       unsigned* __restrict__ cnt)      // [512], pre-zeroed
{
    __shared__ float4 hs4[HID / 4];     // h_{t-1} broadcast copy
    __shared__ float  s_act[32];        // activated gate values per local row
    __shared__ float  c_s[8];
    __shared__ float  h_s[8];

    const int tid   = threadIdx.x;
    const int cta   = blockIdx.x;
    const int base  = cta * 8;
    const int lane  = tid & 31;
    const int warp  = tid >> 5;
    const int row   = warp * 4 + (lane >> 3);   // 0..31
    const int lane8 = lane & 7;
    const int g     = row >> 3;                 // gate (i,f,g,o)
    const int u     = row & 7;                  // unit within CTA

    // Stage 128 weights/thread into registers.
    const float4* wsrc = (const float4*)(Whh + (size_t)(g * HID + base + u) * HID);
    float4 wr[32];
#pragma unroll
    for (int jj = 0; jj < 32; ++jj)
        wr[jj] = __ldg(&wsrc[lane8 + 8 * jj]);

    if (tid < 8) c_s[tid] = 0.f;
    hs4[tid] = make_float4(0.f, 0.f, 0.f, 0.f);

    float xgv = 0.f;
    if (lane8 == 0)
        xgv = __ldg(xg + (size_t)0 * GATES + g * HID + base + u);
    __syncthreads();

    for (int t = 0; t < T_FRAMES; ++t) {
        // ---- dot: 128 weights x h, 4 independent FMA chains ----
        float s0 = 0.f, s1 = 0.f, s2 = 0.f, s3 = 0.f;
#pragma unroll
        for (int jj = 0; jj < 32; ++jj) {
            const float4 h = hs4[lane8 + 8 * jj];
            s0 = fmaf(wr[jj].x, h.x, s0);
            s1 = fmaf(wr[jj].y, h.y, s1);
            s2 = fmaf(wr[jj].z, h.z, s2);
            s3 = fmaf(wr[jj].w, h.w, s3);
        }
        float sum = (s0 + s1) + (s2 + s3);
        sum += __shfl_xor_sync(0xffffffffu, sum, 1);
        sum += __shfl_xor_sync(0xffffffffu, sum, 2);
        sum += __shfl_xor_sync(0xffffffffu, sum, 4);
        if (lane8 == 0) {
            const float a = sum + xgv;
            s_act[row] = (g == 2) ? tanhf(a) : sigmf(a);   // activations in parallel
        }
        __syncthreads();

        // ---- cell/hidden update (warp 0) ----
        if (tid < 8) {
            const float i_ = s_act[tid];
            const float f_ = s_act[8 + tid];
            const float g_ = s_act[16 + tid];
            const float o_ = s_act[24 + tid];
            const float c  = f_ * c_s[tid] + i_ * g_;
            c_s[tid] = c;
            h_s[tid] = o_ * tanhf(c);
        }
        __syncwarp();
        if (tid == 0) {
            float4* dst = (float4*)(hs_out + (size_t)t * HID + base);
            __stcg(dst,     *(float4*)&h_s[0]);
            __stcg(dst + 1, *(float4*)&h_s[4]);
            __threadfence();                       // publish before arrive
            if (t < T_FRAMES - 1) atomicAdd(&cnt[t], 1u);
        }

        if (t == T_FRAMES - 1) break;

        // ---- wait for all 128 CTAs' slices of h_t (one poller per warp) ----
        {
            const volatile unsigned* cp = (const volatile unsigned*)&cnt[t];
            unsigned done;
            do {
                unsigned v = 0;
                if (lane == 0) v = *cp;
                done = (__shfl_sync(0xffffffffu, v, 0) >= (unsigned)NCTA);
            } while (!done);
        }
        __threadfence();                           // acquire

        // ---- fetch assembled h_t, prefetch next xg ----
        hs4[tid] = __ldcg(((const float4*)(hs_out + (size_t)t * HID)) + tid);
        if (lane8 == 0)
            xgv = __ldg(xg + (size_t)(t + 1) * GATES + g * HID + base + u);
        __syncthreads();
    }
}

// ================================ launch =====================================
extern "C" void kernel_launch(void* const* d_in, const int* in_sizes, int n_in,
                              void* d_out, int out_size)
{
    (void)in_sizes; (void)n_in; (void)out_size;

    const float* x       = (const float*)d_in[0];
    const float* W_ih[3] = {(const float*)d_in[1], (const float*)d_in[5], (const float*)d_in[9]};
    const float* W_hh[3] = {(const float*)d_in[2], (const float*)d_in[6], (const float*)d_in[10]};
    const float* b_ih[3] = {(const float*)d_in[3], (const float*)d_in[7], (const float*)d_in[11]};
    const float* b_hh[3] = {(const float*)d_in[4], (const float*)d_in[8], (const float*)d_in[12]};
    const float* W_out   = (const float*)d_in[13];
    float* out = (float*)d_out;

    float *xg, *hsA, *hsB;
    unsigned* cnt;
    cudaGetSymbolAddress((void**)&xg,  g_xg);
    cudaGetSymbolAddress((void**)&hsA, g_hsA);
    cudaGetSymbolAddress((void**)&hsB, g_hsB);
    cudaGetSymbolAddress((void**)&cnt, g_cnt);

    const dim3 blk(256);
    const dim3 grid_xg(GATES / BN, T_FRAMES / BM);                  // (32, 4)
    const dim3 grid_out((OUT_N + BN - 1) / BN, T_FRAMES / BM);      // (162, 4)

    // layer 0
    sgemm128<<<grid_xg, blk>>>(x,   W_ih[0], b_ih[0], b_hh[0], xg,
                               T_FRAMES, GATES, IN_DIM, cnt);
    lstm_layer_kernel<<<NCTA, NTHR>>>(W_hh[0], xg, hsA, cnt);

    // layer 1
    sgemm128<<<grid_xg, blk>>>(hsA, W_ih[1], b_ih[1], b_hh[1], xg,
                               T_FRAMES, GATES, HID, cnt);
    lstm_layer_kernel<<<NCTA, NTHR>>>(W_hh[1], xg, hsB, cnt);

    // layer 2
    sgemm128<<<grid_xg, blk>>>(hsB, W_ih[2], b_ih[2], b_hh[2], xg,
                               T_FRAMES, GATES, HID, cnt);
    lstm_layer_kernel<<<NCTA, NTHR>>>(W_hh[2], xg, hsA, cnt);

    // output projection
    sgemm128<<<grid_out, blk>>>(hsA, W_out, nullptr, nullptr, out,
                                T_FRAMES, OUT_N, HID, nullptr);
}